// round 1
// baseline (speedup 1.0000x reference)
#include <cuda_runtime.h>
#include <stdint.h>

#define HH 1024
#define WW 2048
#define PS 16
#define STR 8
#define NHH 127
#define NWW 255
#define P_TOT (NHH * NWW)   /* 32385 */
#define MARGIN_F 1e-4f
#define WARPS_PER_BLK 8

__device__ double g_loss_sum;
__device__ double g_used;
__device__ int    g_mask_mode;   // 0 = uint8, 1 = float32, 2 = int32

// ---------------------------------------------------------------------------
// Detect mask dtype from byte pattern + zero the accumulators (runs each replay)
// ---------------------------------------------------------------------------
__global__ void detect_zero_kernel(const uint8_t* __restrict__ mask_raw) {
    const uint32_t* w = (const uint32_t*)mask_raw;
    bool anyBig = false;   // any byte with bits above bit0 -> float32 pattern (0x3F800000)
    bool all01  = true;    // every 32-bit word is 0 or 1 -> int32 0/1
    for (int i = 0; i < 256; i++) {
        uint32_t x = w[i];
        if (x & 0xFEFEFEFEu) anyBig = true;
        if (x > 1u)          all01  = false;
    }
    g_mask_mode = anyBig ? 1 : (all01 ? 2 : 0);
    g_loss_sum = 0.0;
    g_used     = 0.0;
}

// ---------------------------------------------------------------------------
// Main kernel: one warp per patch.
//   token = (noise_bits & 0xFFFFFF00) | elem_idx   (masked)
//         = 0xFF000000 | elem_idx                  (unmasked -> sorts last)
//   Bitonic sort 256 tokens across 32 lanes x 8 regs, v = lane + 32*r.
// ---------------------------------------------------------------------------
__global__ __launch_bounds__(256) void patch_loss_kernel(
    const float* __restrict__ pred,
    const float* __restrict__ target,
    const uint8_t* __restrict__ mask_raw,
    const float* __restrict__ noise)
{
    __shared__ float   s_pp[WARPS_PER_BLK][256];
    __shared__ float   s_tp[WARPS_PER_BLK][256];
    __shared__ uint8_t s_m [WARPS_PER_BLK][256];
    __shared__ float   s_blk_loss;
    __shared__ float   s_blk_cnt;

    const int wid  = threadIdx.x >> 5;
    const int lane = threadIdx.x & 31;
    if (threadIdx.x == 0) { s_blk_loss = 0.f; s_blk_cnt = 0.f; }
    __syncthreads();

    const int p = blockIdx.x * WARPS_PER_BLK + wid;
    if (p < P_TOT) {
        const int pi = p / NWW;
        const int pj = p - pi * NWW;
        const int br = pi * STR;
        const int bc = pj * STR;
        const int mode = g_mask_mode;

        uint32_t tok[8];
        bool     mk[8];

        #pragma unroll
        for (int r = 0; r < 8; r++) {
            const int e  = lane + 32 * r;
            const int a  = e >> 4;
            const int b  = e & 15;
            const int gi = (br + a) * WW + (bc + b);
            const float pv = __ldg(pred + gi);
            const float tv = __ldg(target + gi);
            s_pp[wid][e] = pv;
            s_tp[wid][e] = tv;
            bool m;
            if (mode == 0)      m = mask_raw[gi] != 0;
            else if (mode == 1) m = ((const float*)mask_raw)[gi] != 0.0f;
            else                m = ((const int*)mask_raw)[gi] != 0;
            mk[r] = m;
            const float nz = __ldg(noise + (size_t)p * 256 + e);
            const uint32_t kb = __float_as_uint(nz);
            tok[r] = m ? ((kb & 0xFFFFFF00u) | (uint32_t)e)
                       : (0xFF000000u | (uint32_t)e);
        }

        // index-ranks of masked elements via ballots; scatter masked-index list
        const uint32_t lt = (1u << lane) - 1u;
        int pre = 0;
        #pragma unroll
        for (int r = 0; r < 8; r++) {
            const uint32_t bl = __ballot_sync(0xffffffffu, mk[r]);
            const int rk = pre + __popc(bl & lt);
            if (mk[r]) s_m[wid][rk] = (uint8_t)(lane + 32 * r);
            pre += __popc(bl);
        }
        const int K = pre;
        __syncwarp();

        // ---- bitonic sort, ascending; position v = lane + 32*r ----
        #pragma unroll
        for (int k = 2; k <= 256; k <<= 1) {
            #pragma unroll
            for (int j = k >> 1; j >= 1; j >>= 1) {
                if (j >= 32) {
                    const int jr = j >> 5;
                    #pragma unroll
                    for (int r = 0; r < 8; r++) {
                        if ((r & jr) == 0) {
                            const int r2 = r | jr;
                            const bool up = (((lane + 32 * r) & k) == 0);
                            const uint32_t A = tok[r], B = tok[r2];
                            const uint32_t mn = min(A, B), mx = max(A, B);
                            tok[r]  = up ? mn : mx;
                            tok[r2] = up ? mx : mn;
                        }
                    }
                } else {
                    #pragma unroll
                    for (int r = 0; r < 8; r++) {
                        const int v = lane + 32 * r;
                        const uint32_t other = __shfl_xor_sync(0xffffffffu, tok[r], j);
                        const bool takeMin = (((v & k) == 0) == ((v & j) == 0));
                        const uint32_t mn = min(tok[r], other), mx = max(tok[r], other);
                        tok[r] = takeMin ? mn : mx;
                    }
                }
            }
        }
        __syncwarp();

        // ---- hinge epilogue: rank v < K pairs (m[v], sorted_idx[v]) ----
        float loss = 0.f;
        int   cnt  = 0;
        #pragma unroll
        for (int r = 0; r < 8; r++) {
            const int v = lane + 32 * r;
            if (v < K) {
                const int bI = (int)(tok[r] & 0xFFu);
                const int aI = (int)s_m[wid][v];
                const float dt = s_tp[wid][aI] - s_tp[wid][bI];
                const float dp = s_pp[wid][aI] - s_pp[wid][bI] + MARGIN_F;
                const int st = (dt > 0.f) - (dt < 0.f);
                const int sp = (dp > 0.f) - (dp < 0.f);
                if (st != sp) { cnt++; loss += fabsf(dp); }
            }
        }
        #pragma unroll
        for (int o = 16; o; o >>= 1) {
            loss += __shfl_xor_sync(0xffffffffu, loss, o);
            cnt  += __shfl_xor_sync(0xffffffffu, cnt,  o);
        }
        if (lane == 0 && K > 0) {
            atomicAdd(&s_blk_loss, loss / (float)cnt);
            atomicAdd(&s_blk_cnt, 1.0f);
        }
    }
    __syncthreads();
    if (threadIdx.x == 0) {
        atomicAdd(&g_loss_sum, (double)s_blk_loss);
        atomicAdd(&g_used,     (double)s_blk_cnt);
    }
}

__global__ void finalize_kernel(float* __restrict__ out) {
    out[0] = (float)(g_loss_sum / g_used);
}

// ---------------------------------------------------------------------------
extern "C" void kernel_launch(void* const* d_in, const int* in_sizes, int n_in,
                              void* d_out, int out_size) {
    const float*   pred   = (const float*)d_in[0];
    const float*   target = (const float*)d_in[1];
    const uint8_t* mask   = (const uint8_t*)d_in[2];
    const float*   noise  = (const float*)d_in[3];

    detect_zero_kernel<<<1, 1>>>(mask);
    const int nblocks = (P_TOT + WARPS_PER_BLK - 1) / WARPS_PER_BLK;
    patch_loss_kernel<<<nblocks, 256>>>(pred, target, mask, noise);
    finalize_kernel<<<1, 1>>>((float*)d_out);
}